// round 7
// baseline (speedup 1.0000x reference)
#include <cuda_runtime.h>
#include <math_constants.h>

// Problem shape (fixed by the dataset): B=32, H=16, N=1024, D=128, fp32.
#define Bc 32
#define Hc 16
#define Nc 1024
#define Dc 128
#define D4 (Dc / 4)                 // 32 float4 per row
#define NROWS (Bc * Hc * Nc)        // 524288 rows total
#define NT1TILES 8192               // K1: 2048 float4 (64 rows) per block
#define T1_PER_BH (NT1TILES / (Bc * Hc))   // 16 partials per bh

// Scratch (device globals; allocation is forbidden).
__device__ float g_score [NROWS];        // per-row score (t . w2)      2 MB
__device__ float g_part  [NT1TILES];     // per-tile t1.w1 partials     32 KB
__device__ float g_factor[NROWS];        // attn + 1                    2 MB

// ---------------------------------------------------------------------------
// Kernel 1: t1 . w1 partial sums. Pure reduction — no per-row output.
// Thread reads float4s {base+tid, +256, ..., +1792}; all are congruent to
// tid mod 32, so one resident w1 segment per thread, zero shuffle in main path.
// One block = 2048 float4 = 64 rows (within one bh). __ldcs: never reused.
// ---------------------------------------------------------------------------
__global__ __launch_bounds__(256)
void t1sum_kernel(const float* __restrict__ t1,
                  const float* __restrict__ w)      // [256]: w1 | w2
{
    __shared__ float s_red[8];
    const int tid  = threadIdx.x;
    const size_t base = (size_t)blockIdx.x * 2048;
    const float4* tv = reinterpret_cast<const float4*>(t1);
    const float4  wv = reinterpret_cast<const float4*>(w)[tid & 31];

    float acc = 0.f;
    #pragma unroll
    for (int k = 0; k < 8; k++) {
        float4 v = __ldcs(tv + base + tid + k * 256);
        acc += v.x * wv.x + v.y * wv.y + v.z * wv.z + v.w * wv.w;
    }
    #pragma unroll
    for (int o = 16; o > 0; o >>= 1)
        acc += __shfl_xor_sync(0xffffffffu, acc, o);
    if ((tid & 31) == 0) s_red[tid >> 5] = acc;
    __syncthreads();
    if (tid == 0) {
        float p = s_red[0] + s_red[1] + s_red[2] + s_red[3]
                + s_red[4] + s_red[5] + s_red[6] + s_red[7];
        g_part[blockIdx.x] = p;
    }
}

// ---------------------------------------------------------------------------
// Kernel 2: per-row scores (t . w2). Quad-per-warp layout (proven 84% DRAM).
// t read with DEFAULT policy — its tail must survive in L2 for the scale pass.
// ---------------------------------------------------------------------------
__global__ __launch_bounds__(256)
void score_kernel(const float* __restrict__ t,
                  const float* __restrict__ w)
{
    const int warp = (blockIdx.x * blockDim.x + threadIdx.x) >> 5;
    const int lane = threadIdx.x & 31;
    const int g    = lane >> 3;
    const int sub  = lane & 7;
    const int row  = warp * 4 + g;

    const float4* trow = reinterpret_cast<const float4*>(t) + (size_t)row * D4;
    const float4* wf   = reinterpret_cast<const float4*>(w);

    float4 c0 = trow[sub];
    float4 c1 = trow[sub + 8];
    float4 c2 = trow[sub + 16];
    float4 c3 = trow[sub + 24];

    float4 u0 = wf[D4 + sub],      u1 = wf[D4 + sub + 8];
    float4 u2 = wf[D4 + sub + 16], u3 = wf[D4 + sub + 24];

    float sc = c0.x*u0.x + c0.y*u0.y + c0.z*u0.z + c0.w*u0.w
             + c1.x*u1.x + c1.y*u1.y + c1.z*u1.z + c1.w*u1.w
             + c2.x*u2.x + c2.y*u2.y + c2.z*u2.z + c2.w*u2.w
             + c3.x*u3.x + c3.y*u3.y + c3.z*u3.z + c3.w*u3.w;

    sc += __shfl_xor_sync(0xffffffffu, sc, 1);
    sc += __shfl_xor_sync(0xffffffffu, sc, 2);
    sc += __shfl_xor_sync(0xffffffffu, sc, 4);
    if (sub == 0) g_score[row] = sc;
}

// ---------------------------------------------------------------------------
// Kernel 3: one block per (b,h). base from 16 tile partials, padd, softmax,
// factor = attn + 1.  (~6 MB traffic.)
// ---------------------------------------------------------------------------
__global__ __launch_bounds__(256)
void softmax_kernel(const int*   __restrict__ padding,
                    const float* __restrict__ bias)
{
    __shared__ float s_score[Nc];          // 4 KB
    __shared__ float s_red[8];
    __shared__ int   s_padd;

    const int bh   = blockIdx.x;
    const int b    = bh >> 4;              // Hc = 16
    const int tid  = threadIdx.x;
    const int wid  = tid >> 5;
    const int lane = tid & 31;

    if (tid == 0) s_padd = Nc;
    __syncthreads();

    // padd
    {
        const int* pb = padding + b * Nc;
        int local = Nc;
        #pragma unroll
        for (int n = tid; n < Nc; n += 256)
            if (pb[n] == 0) local = min(local, n);
        if (local < Nc) atomicMin(&s_padd, local);
    }

    // base = bias + sum of 16 tile partials (warp 0, fixed-order butterfly)
    if (wid == 0) {
        float v = (lane < T1_PER_BH) ? __ldcs(&g_part[bh * T1_PER_BH + lane]) : 0.f;
        #pragma unroll
        for (int o = 16; o > 0; o >>= 1)
            v += __shfl_xor_sync(0xffffffffu, v, o);
        if (lane == 0) s_red[0] = v;
    }
    __syncthreads();
    const float base = bias[0] + s_red[0];
    const int   padd = s_padd;
    __syncthreads();

    // load scores + max over valid
    const float* sc_g = g_score + bh * Nc;
    float m = -CUDART_INF_F;
    #pragma unroll
    for (int n = tid; n < Nc; n += 256) {
        float sc = __ldcs(sc_g + n) + base;
        s_score[n] = sc;
        if (n < padd) m = fmaxf(m, sc);
    }
    #pragma unroll
    for (int o = 16; o > 0; o >>= 1)
        m = fmaxf(m, __shfl_xor_sync(0xffffffffu, m, o));
    if (lane == 0) s_red[wid] = m;
    __syncthreads();
    float mx = -CUDART_INF_F;
    #pragma unroll
    for (int i = 0; i < 8; i++) mx = fmaxf(mx, s_red[i]);

    float esum = 0.f;
    #pragma unroll
    for (int n = tid; n < Nc; n += 256) {
        float e = (n < padd) ? __expf(s_score[n] - mx) : 0.f;
        s_score[n] = e;
        esum += e;
    }
    #pragma unroll
    for (int o = 16; o > 0; o >>= 1)
        esum += __shfl_xor_sync(0xffffffffu, esum, o);
    __syncthreads();
    if (lane == 0) s_red[wid] = esum;
    __syncthreads();
    float tot = 0.f;
    #pragma unroll
    for (int i = 0; i < 8; i++) tot += s_red[i];
    const float inv = (tot > 0.f) ? (1.f / tot) : 0.f;

    float* fout = g_factor + bh * Nc;
    #pragma unroll
    for (int n = tid; n < Nc; n += 256)
        fout[n] = fmaf(s_score[n], inv, 1.f);
}

// ---------------------------------------------------------------------------
// Kernel 4: out = t * factor[row]. Loop-free tiles, REVERSE order so the
// L2-resident tail of t (just streamed by score_kernel) is consumed first.
// ---------------------------------------------------------------------------
__global__ __launch_bounds__(256)
void scale_kernel(const float* __restrict__ t, float* __restrict__ out)
{
    const int tile = (int)gridDim.x - 1 - (int)blockIdx.x;
    const size_t base = (size_t)tile * 1024;
    const int    tid  = threadIdx.x;
    const float4* tv = reinterpret_cast<const float4*>(t);
    float4* ov = reinterpret_cast<float4*>(out);

    float4 v0 = __ldcs(tv + base + tid);
    float4 v1 = __ldcs(tv + base + tid + 256);
    float4 v2 = __ldcs(tv + base + tid + 512);
    float4 v3 = __ldcs(tv + base + tid + 768);

    const int row0 = (int)(base >> 5) + (tid >> 5);
    float f0 = g_factor[row0];
    float f1 = g_factor[row0 + 8];
    float f2 = g_factor[row0 + 16];
    float f3 = g_factor[row0 + 24];

    v0.x *= f0; v0.y *= f0; v0.z *= f0; v0.w *= f0;
    v1.x *= f1; v1.y *= f1; v1.z *= f1; v1.w *= f1;
    v2.x *= f2; v2.y *= f2; v2.z *= f2; v2.w *= f2;
    v3.x *= f3; v3.y *= f3; v3.z *= f3; v3.w *= f3;

    __stcs(ov + base + tid,       v0);
    __stcs(ov + base + tid + 256, v1);
    __stcs(ov + base + tid + 512, v2);
    __stcs(ov + base + tid + 768, v3);
}

extern "C" void kernel_launch(void* const* d_in, const int* in_sizes, int n_in,
                              void* d_out, int out_size)
{
    const float* t1      = (const float*)d_in[0];
    const float* t       = (const float*)d_in[1];
    const int*   padding = (const int*)d_in[2];

    const float* w = nullptr;
    for (int i = 3; i < n_in; i++)
        if (in_sizes[i] == 2 * Dc) { w = (const float*)d_in[i]; }
    const float* bias = (const float*)d_in[n_in - 1];

    float* out = (float*)d_out;

    t1sum_kernel<<<NT1TILES, 256>>>(t1, w);        // t1 stream first
    score_kernel<<<NROWS / 4 / 8, 256>>>(t, w);    // t stream last -> L2 tail
    softmax_kernel<<<Bc * Hc, 256>>>(padding, bias);
    scale_kernel<<<16384, 256>>>(t, out);          // reverse, eats L2 tail
    (void)out_size;
}